// round 2
// baseline (speedup 1.0000x reference)
#include <cuda_runtime.h>
#include <cuda_bf16.h>
#include <cstdint>

#define L 4096
#define D 1024
#define BATCH 8
#define DK 64
#define BD 8192   /* BATCH*D */
#define PI_F 3.14159265358979f

// ---------------- scratch (static device globals; no allocations) ----------
__device__ float g_m[L * DK];                  // 1 MB   mean vectors [L, DK]
__device__ float g_cs_part[32 * BD];           // 1 MB   colsum partials
__device__ float g_colsum[BD];                 // 32 KB  colsum[b*D+d]
__device__ float g_S[L];                       // 16 KB  softmax denominators
__device__ __nv_bfloat16 g_F[(size_t)L * L];   // 32 MB  F = expm1(logits), bf16
__device__ __nv_bfloat16 g_Xb[(size_t)L * BD]; // 64 MB  x as [j, b*D+d] bf16

// ---------------- helpers --------------------------------------------------
__device__ __forceinline__ uint32_t cvta_s(const void* p) {
    return (uint32_t)__cvta_generic_to_shared(p);
}
__device__ __forceinline__ void cp16(uint32_t dst, const void* src) {
    asm volatile("cp.async.cg.shared.global [%0], [%1], 16;\n" :: "r"(dst), "l"(src));
}
__device__ __forceinline__ void ldm_x4(uint32_t& r0, uint32_t& r1, uint32_t& r2,
                                       uint32_t& r3, uint32_t a) {
    asm volatile("ldmatrix.sync.aligned.m8n8.x4.shared.b16 {%0,%1,%2,%3}, [%4];"
                 : "=r"(r0), "=r"(r1), "=r"(r2), "=r"(r3) : "r"(a));
}
__device__ __forceinline__ void ldm_x4t(uint32_t& r0, uint32_t& r1, uint32_t& r2,
                                        uint32_t& r3, uint32_t a) {
    asm volatile("ldmatrix.sync.aligned.m8n8.x4.trans.shared.b16 {%0,%1,%2,%3}, [%4];"
                 : "=r"(r0), "=r"(r1), "=r"(r2), "=r"(r3) : "r"(a));
}
__device__ __forceinline__ void mma16816(float* c, const uint32_t* a,
                                         uint32_t b0, uint32_t b1) {
    asm volatile(
        "mma.sync.aligned.m16n8k16.row.col.f32.bf16.bf16.f32 "
        "{%0,%1,%2,%3},{%4,%5,%6,%7},{%8,%9},{%0,%1,%2,%3};"
        : "+f"(c[0]), "+f"(c[1]), "+f"(c[2]), "+f"(c[3])
        : "r"(a[0]), "r"(a[1]), "r"(a[2]), "r"(a[3]), "r"(b0), "r"(b1));
}

// ---------------- kernel 1: m[l,d] = mean over (b,h) -----------------------
__global__ void k_mean(const float* __restrict__ x) {
    int t = blockIdx.x * 256 + threadIdx.x;  // 0..262143
    int l = t >> 6, d = t & 63;
    const float* p = x + (size_t)l * D + d;
    float s = 0.f;
#pragma unroll
    for (int b = 0; b < BATCH; b++) {
        const float* pb = p + (size_t)b * L * D;
#pragma unroll
        for (int h = 0; h < 16; h++) s += pb[h * 64];
    }
    g_m[t] = s * (1.0f / 128.0f);
}

// ---------------- kernel 2: colsum partials + bf16 transpose-convert -------
__global__ void k_colsum_conv(const float* __restrict__ x) {
    int bd = blockIdx.x * 256 + threadIdx.x;  // blockIdx.x in [0,32)
    int jc = blockIdx.y;                      // [0,32)
    int b = bd >> 10, d = bd & 1023;
    const float* p = x + (size_t)b * L * D + d;
    int j0 = jc * 128;
    float s = 0.f;
#pragma unroll 8
    for (int jj = 0; jj < 128; jj++) {
        float v = p[(size_t)(j0 + jj) * D];
        s += v;
        g_Xb[(size_t)(j0 + jj) * BD + bd] = __float2bfloat16(v);
    }
    g_cs_part[jc * BD + bd] = s;
}

__global__ void k_colsum_reduce() {
    int bd = blockIdx.x * 256 + threadIdx.x;  // 8192 threads
    float s = 0.f;
#pragma unroll
    for (int jc = 0; jc < 32; jc++) s += g_cs_part[jc * BD + bd];
    g_colsum[bd] = s;
}

// ---------------- kernel 3: F = expm1(sin^2(clip(m m^T)/2)), S = rowsum ----
// Block: 32 rows of i, 256 threads. ty=warp (8) owns rows 4*ty..4*ty+3,
// lane covers j = lane*4..lane*4+3 within each 128-wide j tile.
__global__ __launch_bounds__(256) void k_attn() {
    __shared__ float mIs[64][32];    // k-major, rows of this block
    __shared__ float mJs[64][132];   // k-major, current j tile (pad keeps f4 aligned)
    int tid = threadIdx.x;
    int lane = tid & 31, ty = tid >> 5;
    int iblk = blockIdx.x * 32;

    {   // load mIs (transposed): [k][i_local]
        int il = tid & 31, kq = tid >> 5;
#pragma unroll
        for (int kk = 0; kk < 8; kk++) {
            int k = kq * 8 + kk;
            mIs[k][il] = g_m[(size_t)(iblk + il) * DK + k];
        }
    }
    float fs[4] = {0.f, 0.f, 0.f, 0.f};
    int kL = tid & 63, jh = tid >> 6;

    for (int jt = 0; jt < 32; jt++) {
        __syncthreads();  // protect mJs vs previous tile readers (+ first-use of mIs)
        {   // load mJs transposed: mJs[k][j_local]
            const float* gp = g_m + (size_t)(jt * 128 + jh * 32) * DK + kL;
#pragma unroll 8
            for (int jj = 0; jj < 32; jj++)
                mJs[kL][jh * 32 + jj] = gp[(size_t)jj * DK];
        }
        __syncthreads();

        float acc[4][4];
#pragma unroll
        for (int r = 0; r < 4; r++)
#pragma unroll
            for (int c = 0; c < 4; c++) acc[r][c] = 0.f;

#pragma unroll 16
        for (int k = 0; k < 64; k++) {
            float4 mi4 = *reinterpret_cast<const float4*>(&mIs[k][ty * 4]);
            float4 mj4 = *reinterpret_cast<const float4*>(&mJs[k][lane * 4]);
            float mi[4] = {mi4.x, mi4.y, mi4.z, mi4.w};
            float mj[4] = {mj4.x, mj4.y, mj4.z, mj4.w};
#pragma unroll
            for (int r = 0; r < 4; r++)
#pragma unroll
                for (int c = 0; c < 4; c++)
                    acc[r][c] = fmaf(mi[r], mj[c], acc[r][c]);
        }

#pragma unroll
        for (int r = 0; r < 4; r++) {
            int gi = iblk + ty * 4 + r;
            float f[4];
#pragma unroll
            for (int c = 0; c < 4; c++) {
                float a = fminf(fmaxf(acc[r][c], -PI_F), PI_F);
                float sn = __sinf(0.5f * a);
                float fv = __expf(sn * sn) - 1.0f;
                fs[r] += fv;
                f[c] = fv;
            }
            __nv_bfloat162 p0, p1;
            p0.x = __float2bfloat16(f[0]); p0.y = __float2bfloat16(f[1]);
            p1.x = __float2bfloat16(f[2]); p1.y = __float2bfloat16(f[3]);
            __nv_bfloat162* dst = reinterpret_cast<__nv_bfloat162*>(
                g_F + (size_t)gi * L + jt * 128 + lane * 4);
            dst[0] = p0;
            dst[1] = p1;
        }
    }

    // S[i] = 4096 + sum_j F[i,j]   (warp lanes cover disjoint j sets)
#pragma unroll
    for (int r = 0; r < 4; r++) {
        float v = fs[r];
#pragma unroll
        for (int off = 16; off; off >>= 1) v += __shfl_xor_sync(0xffffffffu, v, off);
        if (lane == 0) g_S[iblk + ty * 4 + r] = 4096.0f + v;
    }
}

// ---------------- kernel 4: out = (colsum + F @ Xb) / S --------------------
// M=4096, N=8192, K=4096, bf16 A/B, fp32 accum. 128x128x32 tiles, 256 thr,
// 8 warps as 2x4 (warp tile 64x32), m16n8k16 mma, 2-stage cp.async pipeline.
__global__ __launch_bounds__(256, 1) void k_gemm(float* __restrict__ out) {
    __shared__ __align__(16) __nv_bfloat16 Asm[2][128][40];  // pad: 80B rows
    __shared__ __align__(16) __nv_bfloat16 Bsm[2][32][136];  // pad: 272B rows
    const int ASTRIDE = 40 * 2, BSTRIDE = 136 * 2;
    const int ASTAGE = 128 * ASTRIDE, BSTAGE = 32 * BSTRIDE;

    int tid = threadIdx.x, lane = tid & 31, warp = tid >> 5;
    int wr = warp >> 2, wc = warp & 3;
    int im0 = blockIdx.y * 128, in0 = blockIdx.x * 128;

    int ar = tid >> 2, ac = (tid & 3) * 8;   // A: rows ar, ar+64
    int br = tid >> 4, bc = (tid & 15) * 8;  // B: rows br, br+16
    const __nv_bfloat16* Ag0 = g_F + (size_t)(im0 + ar) * L + ac;
    const __nv_bfloat16* Ag1 = Ag0 + (size_t)64 * L;
    const __nv_bfloat16* Bg0 = g_Xb + (size_t)br * BD + in0 + bc;
    const __nv_bfloat16* Bg1 = Bg0 + (size_t)16 * BD;

    uint32_t aBase = cvta_s(Asm);
    uint32_t bBase = cvta_s(Bsm);
    uint32_t aDst0 = aBase + ar * ASTRIDE + ac * 2;
    uint32_t aDst1 = aBase + (ar + 64) * ASTRIDE + ac * 2;
    uint32_t bDst0 = bBase + br * BSTRIDE + bc * 2;
    uint32_t bDst1 = bBase + (br + 16) * BSTRIDE + bc * 2;

    // ldmatrix per-lane byte offsets (row = base + lane%16, col-half = lane/16)
    uint32_t aByte = (uint32_t)((wr * 64 + (lane & 15)) * ASTRIDE + (lane >> 4) * 16);
    uint32_t bByte = (uint32_t)((lane & 15) * BSTRIDE + (wc * 32 + (lane >> 4) * 8) * 2);

    float acc[4][4][4];
#pragma unroll
    for (int i = 0; i < 4; i++)
#pragma unroll
        for (int j = 0; j < 4; j++)
#pragma unroll
            for (int q = 0; q < 4; q++) acc[i][j][q] = 0.f;

#define LOADTILE(KT, S)                                        \
    {                                                          \
        int koff = (KT) * 32;                                  \
        cp16(aDst0 + (S) * ASTAGE, Ag0 + koff);                \
        cp16(aDst1 + (S) * ASTAGE, Ag1 + koff);                \
        cp16(bDst0 + (S) * BSTAGE, Bg0 + (size_t)koff * BD);   \
        cp16(bDst1 + (S) * BSTAGE, Bg1 + (size_t)koff * BD);   \
        asm volatile("cp.async.commit_group;\n");              \
    }

    LOADTILE(0, 0);
    const int KT = L / 32;  // 128
    for (int kt = 0; kt < KT; kt++) {
        int s = kt & 1;
        if (kt < KT - 1) {
            LOADTILE(kt + 1, s ^ 1);
            asm volatile("cp.async.wait_group 1;\n");
        } else {
            asm volatile("cp.async.wait_group 0;\n");
        }
        __syncthreads();
        uint32_t aS = aBase + s * ASTAGE + aByte;
        uint32_t bS = bBase + s * BSTAGE + bByte;
#pragma unroll
        for (int kk = 0; kk < 2; kk++) {
            uint32_t af[4][4], bf[2][4];
#pragma unroll
            for (int mt = 0; mt < 4; mt++)
                ldm_x4(af[mt][0], af[mt][1], af[mt][2], af[mt][3],
                       aS + mt * (16 * ASTRIDE) + kk * 32);
#pragma unroll
            for (int ng = 0; ng < 2; ng++)
                ldm_x4t(bf[ng][0], bf[ng][1], bf[ng][2], bf[ng][3],
                        bS + kk * (16 * BSTRIDE) + ng * 32);
#pragma unroll
            for (int mt = 0; mt < 4; mt++)
#pragma unroll
                for (int nt = 0; nt < 4; nt++)
                    mma16816(acc[mt][nt], af[mt],
                             bf[nt >> 1][(nt & 1) * 2], bf[nt >> 1][(nt & 1) * 2 + 1]);
        }
        __syncthreads();
    }
#undef LOADTILE

    // epilogue: out[b,i,d] = (colsum[b*D+d] + acc) / S[i]
#pragma unroll
    for (int mt = 0; mt < 4; mt++) {
        int r0 = im0 + wr * 64 + mt * 16 + (lane >> 2);
        float is0 = 1.0f / g_S[r0];
        float is1 = 1.0f / g_S[r0 + 8];
#pragma unroll
        for (int nt = 0; nt < 4; nt++) {
            int n = in0 + wc * 32 + nt * 8 + (lane & 3) * 2;
            float cs0 = g_colsum[n], cs1 = g_colsum[n + 1];
            int b = n >> 10, d = n & 1023;
            float* o0 = out + ((size_t)b * L + r0) * D + d;
            float* o1 = o0 + 8 * D;
            float2 v0 = make_float2((cs0 + acc[mt][nt][0]) * is0,
                                    (cs1 + acc[mt][nt][1]) * is0);
            float2 v1 = make_float2((cs0 + acc[mt][nt][2]) * is1,
                                    (cs1 + acc[mt][nt][3]) * is1);
            *reinterpret_cast<float2*>(o0) = v0;
            *reinterpret_cast<float2*>(o1) = v1;
        }
    }
}

// ---------------- launch ---------------------------------------------------
extern "C" void kernel_launch(void* const* d_in, const int* in_sizes, int n_in,
                              void* d_out, int out_size) {
    (void)in_sizes; (void)n_in; (void)out_size;
    const float* x = (const float*)d_in[0];
    float* out = (float*)d_out;

    k_mean<<<1024, 256>>>(x);                    // g_m
    k_colsum_conv<<<dim3(32, 32), 256>>>(x);     // g_cs_part, g_Xb
    k_colsum_reduce<<<32, 256>>>();              // g_colsum
    k_attn<<<128, 256>>>();                      // g_F, g_S
    k_gemm<<<dim3(64, 32), 256>>>(out);          // out
}

// round 5
// speedup vs baseline: 1.3456x; 1.3456x over previous
#include <cuda_runtime.h>
#include <cuda_bf16.h>
#include <cuda_fp8.h>
#include <cstdint>

#define L 4096
#define D 1024
#define BATCH 8
#define DK 64
#define BD 8192   /* BATCH*D */
#define PI_F 3.14159265358979f

// ---------------- scratch (static device globals; no allocations) ----------
__device__ float g_m[L * DK];                       // 1 MB   mean vectors [L, DK]
__device__ float g_cs_part[64 * BD];                // 2 MB   colsum partials
__device__ float g_colsum[BD];                      // 32 KB  colsum[b*D+d]
__device__ float g_S[L];                            // 16 KB  softmax denominators
__device__ __align__(16) uint8_t g_F8[(size_t)L * L];    // 16 MB  F=expm1(logits) e4m3 [i,j]
__device__ __align__(16) uint8_t g_Xn8[(size_t)BD * L];  // 32 MB  x^T e4m3 [b*D+d, j]

// ---------------- PTX helpers ----------------------------------------------
__device__ __forceinline__ uint32_t cvta_s(const void* p) {
    return (uint32_t)__cvta_generic_to_shared(p);
}
__device__ __forceinline__ void cp16(uint32_t dst, const void* src) {
    asm volatile("cp.async.cg.shared.global [%0], [%1], 16;\n" :: "r"(dst), "l"(src));
}
__device__ __forceinline__ void cp_commit() {
    asm volatile("cp.async.commit_group;\n");
}
template <int N_>
__device__ __forceinline__ void cp_wait() {
    asm volatile("cp.async.wait_group %0;\n" :: "n"(N_));
}
__device__ __forceinline__ void ldm_x4(uint32_t& r0, uint32_t& r1, uint32_t& r2,
                                       uint32_t& r3, uint32_t a) {
    asm volatile("ldmatrix.sync.aligned.m8n8.x4.shared.b16 {%0,%1,%2,%3}, [%4];"
                 : "=r"(r0), "=r"(r1), "=r"(r2), "=r"(r3) : "r"(a));
}
__device__ __forceinline__ void ldm_x2(uint32_t& r0, uint32_t& r1, uint32_t a) {
    asm volatile("ldmatrix.sync.aligned.m8n8.x2.shared.b16 {%0,%1}, [%2];"
                 : "=r"(r0), "=r"(r1) : "r"(a));
}
// fp8 e4m3 mma: m16n8k32, A row-major (4 regs), B col-major (2 regs), f32 acc
__device__ __forceinline__ void mma32f8(float* c, const uint32_t* a,
                                        uint32_t b0, uint32_t b1) {
    asm volatile(
        "mma.sync.aligned.m16n8k32.row.col.f32.e4m3.e4m3.f32 "
        "{%0,%1,%2,%3},{%4,%5,%6,%7},{%8,%9},{%0,%1,%2,%3};"
        : "+f"(c[0]), "+f"(c[1]), "+f"(c[2]), "+f"(c[3])
        : "r"(a[0]), "r"(a[1]), "r"(a[2]), "r"(a[3]), "r"(b0), "r"(b1));
}
__device__ __forceinline__ uint32_t f2fp8(float v) {
    return (uint32_t)__nv_cvt_float_to_fp8(v, __NV_SATFINITE, __NV_E4M3);
}

// ---------------- kernel 1: m[l,d] = mean over (b,h) -----------------------
__global__ void k_mean(const float* __restrict__ x) {
    int t = blockIdx.x * 256 + threadIdx.x;  // 0..262143
    int l = t >> 6, d = t & 63;
    const float* p = x + (size_t)l * D + d;
    float s = 0.f;
#pragma unroll
    for (int b = 0; b < BATCH; b++) {
        const float* pb = p + (size_t)b * L * D;
#pragma unroll
        for (int h = 0; h < 16; h++) s += pb[h * 64];
    }
    g_m[t] = s * (1.0f / 128.0f);
}

// ---------------- kernel 2: transpose x -> g_Xn8[bd, j] (e4m3) + colsums ---
__global__ __launch_bounds__(256) void k_transpose(const float* __restrict__ x) {
    __shared__ float tile[64][68];
    __shared__ float ps[64][9];
    int tid = threadIdx.x;
    int bd0 = blockIdx.x * 64;
    int j0 = blockIdx.y * 64;
    int b = bd0 >> 10, d0 = bd0 & 1023;
    const float* src = x + (size_t)b * L * D + (size_t)j0 * D + d0;

#pragma unroll
    for (int k = 0; k < 4; k++) {
        int id = tid + k * 256;            // 1024 float4 chunks
        int jr = id >> 4, c4 = id & 15;
        float4 v = *reinterpret_cast<const float4*>(src + (size_t)jr * D + c4 * 4);
        *reinterpret_cast<float4*>(&tile[jr][c4 * 4]) = v;
    }
    __syncthreads();

#pragma unroll
    for (int k = 0; k < 2; k++) {
        int id = tid + k * 256;            // 512 chunks of 8 j-values
        int br = id >> 3, jc = id & 7;
        float s = 0.f;
        uint32_t lo = 0, hi = 0;
#pragma unroll
        for (int jj = 0; jj < 8; jj++) {
            float v = tile[jc * 8 + jj][br];
            s += v;
            uint32_t q = f2fp8(v);
            if (jj < 4) lo |= q << (8 * jj);
            else        hi |= q << (8 * (jj - 4));
        }
        ps[br][jc] = s;
        *reinterpret_cast<uint2*>(&g_Xn8[(size_t)(bd0 + br) * L + j0 + jc * 8]) =
            make_uint2(lo, hi);
    }
    __syncthreads();
    if (tid < 64) {
        float s = 0.f;
#pragma unroll
        for (int jc = 0; jc < 8; jc++) s += ps[tid][jc];
        g_cs_part[(size_t)blockIdx.y * BD + bd0 + tid] = s;
    }
}

__global__ void k_colsum_reduce() {
    int bd = blockIdx.x * 256 + threadIdx.x;  // 8192 threads
    float s = 0.f;
#pragma unroll
    for (int jc = 0; jc < 64; jc++) s += g_cs_part[(size_t)jc * BD + bd];
    g_colsum[bd] = s;
}

// ---------------- kernel 3: F = expm1(sin^2(clip(m m^T)/2)), S = rowsum ----
// grid 256 blocks, 16 i-rows each. Single MUFU (SIN) per element; expm1 via
// degree-5 Taylor (s = sin^2 <= ~0.2 in practice; err < 1e-6 there).
__global__ __launch_bounds__(256) void k_attn() {
    __shared__ float mIs[64][16];
    __shared__ float mJs[64][132];
    int tid = threadIdx.x;
    int lane = tid & 31, ty = tid >> 5;
    int iblk = blockIdx.x * 16;

#pragma unroll
    for (int k = 0; k < 4; k++) {
        int id = tid + k * 256;            // 1024 = 16 rows x 64 k
        int row = id & 15, kc = id >> 4;
        mIs[kc][row] = g_m[(size_t)(iblk + row) * DK + kc];
    }
    float fs[2] = {0.f, 0.f};
    int kL = tid & 63, jh = tid >> 6;

    for (int jt = 0; jt < 32; jt++) {
        __syncthreads();
        {
            const float* gp = g_m + (size_t)(jt * 128 + jh * 32) * DK + kL;
#pragma unroll 8
            for (int jj = 0; jj < 32; jj++)
                mJs[kL][jh * 32 + jj] = gp[(size_t)jj * DK];
        }
        __syncthreads();

        float acc[2][4];
#pragma unroll
        for (int r = 0; r < 2; r++)
#pragma unroll
            for (int c = 0; c < 4; c++) acc[r][c] = 0.f;

#pragma unroll 16
        for (int k = 0; k < 64; k++) {
            float2 mi2 = *reinterpret_cast<const float2*>(&mIs[k][ty * 2]);
            float4 mj4 = *reinterpret_cast<const float4*>(&mJs[k][lane * 4]);
            float mj[4] = {mj4.x, mj4.y, mj4.z, mj4.w};
#pragma unroll
            for (int c = 0; c < 4; c++) {
                acc[0][c] = fmaf(mi2.x, mj[c], acc[0][c]);
                acc[1][c] = fmaf(mi2.y, mj[c], acc[1][c]);
            }
        }

#pragma unroll
        for (int r = 0; r < 2; r++) {
            int gi = iblk + ty * 2 + r;
            uint32_t pk = 0;
#pragma unroll
            for (int c = 0; c < 4; c++) {
                float a = fminf(fmaxf(acc[r][c], -PI_F), PI_F);
                float sn = __sinf(0.5f * a);
                float s = sn * sn;
                // expm1(s) = s + s^2*(1/2 + s*(1/6 + s*(1/24 + s/120)))
                float p = 0.5f + s * (0.16666667f + s * (0.041666668f + s * 0.008333334f));
                float fv = fmaf(s * s, p, s);
                fs[r] += fv;
                pk |= f2fp8(fv) << (8 * c);
            }
            *reinterpret_cast<uint32_t*>(&g_F8[(size_t)gi * L + jt * 128 + lane * 4]) = pk;
        }
    }

#pragma unroll
    for (int r = 0; r < 2; r++) {
        float v = fs[r];
#pragma unroll
        for (int off = 16; off; off >>= 1) v += __shfl_xor_sync(0xffffffffu, v, off);
        if (lane == 0) g_S[iblk + ty * 2 + r] = 4096.0f + v;
    }
}

// ---------------- kernel 4: fp8 GEMM: out = (colsum + F @ x)/S -------------
// CTA tile 128(M) x 256(N), K-chunk 128 (bytes==elems). 3-stage cp.async.
// 8 warps = 2x4, warp tile 64x64, mma.m16n8k32 e4m3.
#define ASZ (128 * 128)        /* 16 KB */
#define BSZ (256 * 128)        /* 32 KB */
#define SSZ (ASZ + BSZ)        /* 48 KB */
#define NST 3
#define SMEM_G (NST * SSZ)     /* 144 KB */
#define KSTEPS 32              /* 4096 / 128 */

__global__ __launch_bounds__(256, 1) void k_gemm8(float* __restrict__ out) {
    extern __shared__ __align__(1024) uint8_t dsm[];
    uint32_t sb = cvta_s(dsm);
    int tid = threadIdx.x, lane = tid & 31, warp = tid >> 5;
    int wr = warp >> 2, wc = warp & 3;
    int m0 = blockIdx.y * 128, n0 = blockIdx.x * 256;

    // per-thread cp.async assignments (16B chunks, xor-swizzled by row)
    const uint8_t* aSrc[4]; uint32_t aOff[4];
#pragma unroll
    for (int k = 0; k < 4; k++) {
        int id = tid + k * 256;            // 1024 = 128 rows x 8 chunks
        int r = id >> 3, c = id & 7;
        aSrc[k] = g_F8 + (size_t)(m0 + r) * L + c * 16;
        aOff[k] = (uint32_t)(r * 128 + ((c ^ (r & 7)) << 4));
    }
    const uint8_t* bSrc[8]; uint32_t bOff[8];
#pragma unroll
    for (int k = 0; k < 8; k++) {
        int id = tid + k * 256;            // 2048 = 256 rows x 8 chunks
        int r = id >> 3, c = id & 7;
        bSrc[k] = g_Xn8 + (size_t)(n0 + r) * L + c * 16;
        bOff[k] = (uint32_t)(r * 128 + ((c ^ (r & 7)) << 4));
    }

#define LOADSTAGE(KT, S)                                         \
    {                                                            \
        uint32_t ab = sb + (S) * SSZ, bb = ab + ASZ;             \
        int ko = (KT) * 128;                                     \
        _Pragma("unroll")                                        \
        for (int k = 0; k < 4; k++) cp16(ab + aOff[k], aSrc[k] + ko); \
        _Pragma("unroll")                                        \
        for (int k = 0; k < 8; k++) cp16(bb + bOff[k], bSrc[k] + ko); \
        cp_commit();                                             \
    }

    float acc[4][8][4];
#pragma unroll
    for (int i = 0; i < 4; i++)
#pragma unroll
        for (int j = 0; j < 8; j++)
#pragma unroll
            for (int q = 0; q < 4; q++) acc[i][j][q] = 0.f;

    // precompute ldmatrix lane addresses (byte offsets within a stage)
    uint32_t aLd[4][4], bLd[8][4];   // [mt or nt][kk]
#pragma unroll
    for (int mt = 0; mt < 4; mt++) {
        int row = wr * 64 + mt * 16 + (lane & 15);
#pragma unroll
        for (int kk = 0; kk < 4; kk++) {
            int ch = kk * 2 + (lane >> 4);
            aLd[mt][kk] = (uint32_t)(row * 128 + ((ch ^ (row & 7)) << 4));
        }
    }
#pragma unroll
    for (int nt = 0; nt < 8; nt++) {
        int row = wc * 64 + nt * 8 + (lane & 7);
#pragma unroll
        for (int kk = 0; kk < 4; kk++) {
            int ch = kk * 2 + ((lane >> 3) & 1);
            bLd[nt][kk] = (uint32_t)(ASZ + row * 128 + ((ch ^ (row & 7)) << 4));
        }
    }

    LOADSTAGE(0, 0);
    LOADSTAGE(1, 1);

    for (int kt = 0; kt < KSTEPS; kt++) {
        int s = kt % NST;
        if (kt == KSTEPS - 1) cp_wait<0>(); else cp_wait<1>();
        __syncthreads();
        if (kt + 2 < KSTEPS) LOADSTAGE(kt + 2, (kt + 2) % NST);

        uint32_t stg = sb + s * SSZ;
#pragma unroll
        for (int kk = 0; kk < 4; kk++) {
            uint32_t af[4][4];
#pragma unroll
            for (int mt = 0; mt < 4; mt++)
                ldm_x4(af[mt][0], af[mt][1], af[mt][2], af[mt][3],
                       stg + aLd[mt][kk]);
            uint32_t bfr[8][2];
#pragma unroll
            for (int nt = 0; nt < 8; nt++)
                ldm_x2(bfr[nt][0], bfr[nt][1], stg + bLd[nt][kk]);
#pragma unroll
            for (int mt = 0; mt < 4; mt++)
#pragma unroll
                for (int nt = 0; nt < 8; nt++)
                    mma32f8(acc[mt][nt], af[mt], bfr[nt][0], bfr[nt][1]);
        }
    }
#undef LOADSTAGE

    // epilogue: out[b,i,d] = (colsum[b*D+d] + acc) / S[i]
#pragma unroll
    for (int mt = 0; mt < 4; mt++) {
        int r0 = m0 + wr * 64 + mt * 16 + (lane >> 2);
        float is0 = 1.0f / g_S[r0];
        float is1 = 1.0f / g_S[r0 + 8];
#pragma unroll
        for (int nt = 0; nt < 8; nt++) {
            int n = n0 + wc * 64 + nt * 8 + (lane & 3) * 2;
            float2 cs = *reinterpret_cast<const float2*>(&g_colsum[n]);
            int b = n >> 10, d = n & 1023;
            float* o0 = out + ((size_t)b * L + r0) * D + d;
            float* o1 = o0 + 8 * D;
            float2 v0 = make_float2((cs.x + acc[mt][nt][0]) * is0,
                                    (cs.y + acc[mt][nt][1]) * is0);
            float2 v1 = make_float2((cs.x + acc[mt][nt][2]) * is1,
                                    (cs.y + acc[mt][nt][3]) * is1);
            *reinterpret_cast<float2*>(o0) = v0;
            *reinterpret_cast<float2*>(o1) = v1;
        }
    }
}

// ---------------- launch ---------------------------------------------------
extern "C" void kernel_launch(void* const* d_in, const int* in_sizes, int n_in,
                              void* d_out, int out_size) {
    (void)in_sizes; (void)n_in; (void)out_size;
    const float* x = (const float*)d_in[0];
    float* out = (float*)d_out;

    cudaFuncSetAttribute(k_gemm8, cudaFuncAttributeMaxDynamicSharedMemorySize,
                         SMEM_G);

    k_mean<<<1024, 256>>>(x);                        // g_m
    k_transpose<<<dim3(BD / 64, L / 64), 256>>>(x);  // g_Xn8, g_cs_part
    k_colsum_reduce<<<32, 256>>>();                  // g_colsum
    k_attn<<<256, 256>>>();                          // g_F8, g_S
    k_gemm8<<<dim3(32, 32), 256, SMEM_G>>>(out);     // out
}